// round 15
// baseline (speedup 1.0000x reference)
#include <cuda_runtime.h>

// Quanv layer, circuit collapsed to per-qubit Bloch components + Pauli strings:
//   out_q = cos(p_{3+q}) * <Z_q>_w  -  sin(p_{3+q}) * <X_q>_w
// Persistent software-pipelined kernel, 1 patch/iter + 1 prefetch:
// 740 CTAs x 384 thr = 148 SMs x 5 CTAs (1920 thr/SM, reg budget 34).
// Pipeline hides the ~250-cyc L2 latency behind compute (proved in R14)
// while the narrow register footprint keeps ~94% theoretical occupancy.
// MUFU trig (abs err ~5e-7, tol 1e-3).

__device__ __forceinline__ float4 quanv_one(
    float4 a, float Cp0, float p1, float Cp2,
    float4 C, float4 S)
{
    const float PI = 3.14159265358979323846f;

    // Per-qubit Bloch (x, z) after encoding RY(pi*a_q) + layer-1 gate.
    float t0 = a.x * PI;
    float x0 = __sinf(t0);              // RX leaves X
    float z0 = Cp0 * __cosf(t0);        // RX: z' = cos(p0) * z   (y = 0)

    float t1 = fmaf(a.y, PI, p1);       // RY(p1) adds angles
    float x1 = __sinf(t1);
    float z1 = __cosf(t1);

    float t2 = a.z * PI;
    float x2 = Cp2 * __sinf(t2);        // RZ: x' = cos(p2) * x
    float z2 = __cosf(t2);              // RZ leaves Z

    float t3 = a.w * PI;
    float x3 = __cosf(t3);              // H swaps X <-> Z
    float z3 = __sinf(t3);

    // Pauli strings after conjugating Z_q / X_q through the CNOT ring.
    float z01 = z0 * z1;
    float z23 = z2 * z3;
    float Z0w = z1 * z23;               // Z1 Z2 Z3
    float Z1w = z01;                    // Z0 Z1
    float Z2w = z01 * z2;               // Z0 Z1 Z2
    float Z3w = z01 * z23;              // Z0 Z1 Z2 Z3

    float x01 = x0 * x1;
    float X0w = x01;                    // X0 X1
    float X1w = x1 * x2;                // X1 X2
    float X2w = x2 * x3;                // X2 X3
    float X3w = x01 * x3;               // X0 X1 X3

    float4 o;
    o.x = fmaf(C.x, Z0w, -S.x * X0w);
    o.y = fmaf(C.y, Z1w, -S.y * X1w);
    o.z = fmaf(C.z, Z2w, -S.z * X2w);
    o.w = fmaf(C.w, Z3w, -S.w * X3w);
    return o;
}

__global__ __launch_bounds__(384, 5) void quanv_kernel(
    const float* __restrict__ x,      // [n, 4] angles
    const float* __restrict__ params, // [7]
    float* __restrict__ out,          // [n, 4]
    int n)
{
    const float4* xin = (const float4*)x;
    float4* xout = (float4*)out;

    int idx = blockIdx.x * blockDim.x + threadIdx.x;
    int T = gridDim.x * blockDim.x;

    // Prime: first load in flight during the uniform param prologue.
    float4 a = xin[(idx < n) ? idx : 0];

    // Uniform param constants (broadcast loads + MUFU), hoisted once.
    float p0 = __ldg(params + 0);
    float p1 = __ldg(params + 1);
    float p2 = __ldg(params + 2);
    float p3 = __ldg(params + 3);
    float p4 = __ldg(params + 4);
    float p5 = __ldg(params + 5);
    float p6 = __ldg(params + 6);

    float Cp0 = __cosf(p0);
    float Cp2 = __cosf(p2);
    float4 C, S;
    C.x = __cosf(p3); S.x = __sinf(p3);
    C.y = __cosf(p4); S.y = __sinf(p4);
    C.z = __cosf(p5); S.z = __sinf(p5);
    C.w = __cosf(p6); S.w = __sinf(p6);

    for (int i = idx; i < n; i += T) {
        // Prefetch next iteration (clamped -> always valid; dead on the
        // final iteration but harmless).
        int ni = i + T;
        float4 b = xin[(ni < n) ? ni : 0];

        // Compute current patch while b is in flight.
        xout[i] = quanv_one(a, Cp0, p1, Cp2, C, S);

        a = b;
    }
}

extern "C" void kernel_launch(void* const* d_in, const int* in_sizes, int n_in,
                              void* d_out, int out_size)
{
    const float* x      = (const float*)d_in[0];   // [2048,3,196,4] fp32
    const float* params = (const float*)d_in[1];   // [7] fp32
    float* out = (float*)d_out;                    // flat [n,4] fp32

    int n = in_sizes[0] / 4;       // patches
    int threads = 384;
    int blocks = 740;              // 148 SMs x 5 CTAs (reg budget 34)
    int maxBlocks = (n + threads - 1) / threads;
    if (blocks > maxBlocks) blocks = maxBlocks;
    if (blocks < 1) blocks = 1;
    quanv_kernel<<<blocks, threads>>>(x, params, out, n);
}